// round 2
// baseline (speedup 1.0000x reference)
#include <cuda_runtime.h>

// CPHASE on qubits (0,1) of a 22-qubit batched state (B=4).
// Qubits (0,1) are the slowest axes => |11> subspace = last quarter of flat array.
// Batch (B=4) is innermost => one float4 = one amplitude's 4 batch lanes.
//
// out[0 : 2^24]      = new re plane
// out[2^24 : 2^25]   = new im plane
//
// R2: ILP x2 (4 front-batched LDG.128 per thread) + streaming ld/st hints.

#define N4     (1u << 22)          // float4 count per plane
#define THRESH (3u << 20)          // float4s below this: identity
#define TPB    256u
#define PER_BLK (2u * TPB)         // 512 float4s per block (divides THRESH)

__global__ __launch_bounds__(TPB) void cphase_kernel(
    const float4* __restrict__ re,
    const float4* __restrict__ im,
    const float*  __restrict__ theta,
    float4* __restrict__ out)
{
    const unsigned j0 = blockIdx.x * PER_BLK + threadIdx.x;
    const unsigned j1 = j0 + TPB;

    // Front-batch all 4 loads (MLP_p1 = 4), streaming (no reuse).
    float4 r0 = __ldcs(re + j0);
    float4 r1 = __ldcs(re + j1);
    float4 m0 = __ldcs(im + j0);
    float4 m1 = __ldcs(im + j1);

    if (j0 >= THRESH) {
        // |11> block: rotate each batch lane by theta[b]
        float c0, s0, c1, s1, c2, s2, c3, s3;
        __sincosf(theta[0], &s0, &c0);
        __sincosf(theta[1], &s1, &c1);
        __sincosf(theta[2], &s2, &c2);
        __sincosf(theta[3], &s3, &c3);

        float4 a, b;
        a.x = fmaf(r0.x, c0, -m0.x * s0);  b.x = fmaf(r0.x, s0, m0.x * c0);
        a.y = fmaf(r0.y, c1, -m0.y * s1);  b.y = fmaf(r0.y, s1, m0.y * c1);
        a.z = fmaf(r0.z, c2, -m0.z * s2);  b.z = fmaf(r0.z, s2, m0.z * c2);
        a.w = fmaf(r0.w, c3, -m0.w * s3);  b.w = fmaf(r0.w, s3, m0.w * c3);
        r0 = a; m0 = b;

        a.x = fmaf(r1.x, c0, -m1.x * s0);  b.x = fmaf(r1.x, s0, m1.x * c0);
        a.y = fmaf(r1.y, c1, -m1.y * s1);  b.y = fmaf(r1.y, s1, m1.y * c1);
        a.z = fmaf(r1.z, c2, -m1.z * s2);  b.z = fmaf(r1.z, s2, m1.z * c2);
        a.w = fmaf(r1.w, c3, -m1.w * s3);  b.w = fmaf(r1.w, s3, m1.w * c3);
        r1 = a; m1 = b;
    }

    __stcs(out + j0,       r0);   // re plane
    __stcs(out + j1,       r1);
    __stcs(out + j0 + N4,  m0);   // im plane
    __stcs(out + j1 + N4,  m1);
}

extern "C" void kernel_launch(void* const* d_in, const int* in_sizes, int n_in,
                              void* d_out, int out_size)
{
    const float4* re    = (const float4*)d_in[0];
    const float4* im    = (const float4*)d_in[1];
    const float*  theta = (const float*)d_in[2];
    float4* out = (float4*)d_out;

    cphase_kernel<<<N4 / PER_BLK, TPB>>>(re, im, theta, out);
}